// round 11
// baseline (speedup 1.0000x reference)
#include <cuda_runtime.h>
#include <math.h>

typedef unsigned long long ull;

#define NUMV 2048
#define CDIM 256
#define BSZ 2
#define NHEAD 8
#define NUM_LAYER 4

// ---------------- scratch (static device globals; allowed by rules) --------
__device__ float g_Q[BSZ * CDIM * NUMV];                 // 4 MB  [b][c][n]
__device__ float g_K[BSZ * CDIM * NUMV];                 // 4 MB  [b][c][n]
__device__ float g_S[(size_t)BSZ * NUMV * NUMV];         // 33.5 MB score [b][o][i]
__device__ float g_colW[BSZ * NUMV];                     // column sums of W

// ---------------- f32x2 helpers (Blackwell packed fp32, RN rounding) --------
__device__ __forceinline__ ull dup2(float x) {
    ull d; unsigned u = __float_as_uint(x);
    asm("mov.b64 %0, {%1, %1};" : "=l"(d) : "r"(u));
    return d;
}
__device__ __forceinline__ ull pack2(float x, float y) {
    ull d;
    asm("mov.b64 %0, {%1, %2};" : "=l"(d)
        : "r"(__float_as_uint(x)), "r"(__float_as_uint(y)));
    return d;
}
__device__ __forceinline__ ull fma2(ull a, ull b, ull c) {
    ull d; asm("fma.rn.f32x2 %0, %1, %2, %3;" : "=l"(d) : "l"(a), "l"(b), "l"(c));
    return d;
}
__device__ __forceinline__ ull add2(ull a, ull b) {
    ull d; asm("add.rn.f32x2 %0, %1, %2;" : "=l"(d) : "l"(a), "l"(b));
    return d;
}
__device__ __forceinline__ ull mul2(ull a, ull b) {
    ull d; asm("mul.rn.f32x2 %0, %1, %2;" : "=l"(d) : "l"(a), "l"(b));
    return d;
}
__device__ __forceinline__ void unpack2(ull v, float &x, float &y) {
    unsigned lo, hi;
    asm("mov.b64 {%0, %1}, %2;" : "=r"(lo), "=r"(hi) : "l"(v));
    x = __uint_as_float(lo); y = __uint_as_float(hi);
}

// ---------------- XLA-replica sigmoid -------------------------------------
// Reference chain: x = attn / f32(sqrt(32))   (IEEE RN division)
//                  logistic(x) = 0.5 + 0.5 * fast_tanh(0.5 * x)
// fast_tanh = XLA EmitFastTanh: |t|<4e-4 -> t; clamp [-9,9]; rational poly
// with NON-contracted mul/add Horner; fp32 RN division.
__device__ __forceinline__ ull sigmoid_pair(float ax, float ay) {
    const float SQ32 = 5.656854249492380195f;   // rounds to f32(np.sqrt(32))
    float x0 = __fdiv_rn(ax, SQ32);
    float x1 = __fdiv_rn(ay, SQ32);
    float h0 = __fmul_rn(0.5f, x0);
    float h1 = __fmul_rn(0.5f, x1);
    float c0 = fminf(fmaxf(h0, -9.0f), 9.0f);
    float c1 = fminf(fmaxf(h1, -9.0f), 9.0f);
    ull  cc  = pack2(c0, c1);
    ull  x2  = mul2(cc, cc);
    // numerator Horner (separate mul/add, RN)
    ull p = dup2(-2.76076847742355e-16f);
    p = add2(mul2(p, x2), dup2( 2.00018790482477e-13f));
    p = add2(mul2(p, x2), dup2(-8.60467152213735e-11f));
    p = add2(mul2(p, x2), dup2( 5.12229709037114e-08f));
    p = add2(mul2(p, x2), dup2( 1.48572235717979e-05f));
    p = add2(mul2(p, x2), dup2( 6.37261928875436e-04f));
    p = add2(mul2(p, x2), dup2( 4.89352455891786e-03f));
    ull num = mul2(cc, p);
    // denominator Horner
    ull q = dup2(1.19825839466702e-06f);
    q = add2(mul2(q, x2), dup2(1.18534705686654e-04f));
    q = add2(mul2(q, x2), dup2(2.26843463243900e-03f));
    q = add2(mul2(q, x2), dup2(4.89352518554385e-03f));
    float n0, n1, d0, d1;
    unpack2(num, n0, n1); unpack2(q, d0, d1);
    float t0 = __fdiv_rn(n0, d0);
    float t1 = __fdiv_rn(n1, d1);
    if (fabsf(h0) < 0.0004f) t0 = h0;
    if (fabsf(h1) < 0.0004f) t1 = h1;
    float s0 = __fadd_rn(0.5f, __fmul_rn(0.5f, t0));
    float s1 = __fadd_rn(0.5f, __fmul_rn(0.5f, t1));
    return pack2(s0, s1);
}

// ======================= 1) projections =====================================
// Out[b][o][n] = W @ X + bias.  Sequential ascending-k fp32 FMA chain per
// output element (matches Eigen/XLA gebp accumulation order bit-for-bit).
__global__ void __launch_bounds__(256)
proj_kernel(const float* __restrict__ vf, const float* __restrict__ ef,
            const float* __restrict__ Wq, const float* __restrict__ bq,
            const float* __restrict__ Wk, const float* __restrict__ bk) {
    __shared__ float Ws[128][33];   // [o][c] padded
    __shared__ float Xs[32][128];   // [c][n]

    const int zb = blockIdx.z;
    const int b = zb & 1, which = zb >> 1;
    const float* X    = (which ? ef : vf) + (size_t)b * CDIM * NUMV;
    const float* Wm   = which ? Wk : Wq;
    const float* bias = which ? bk : bq;
    float* Out = (which ? g_K : g_Q) + (size_t)b * CDIM * NUMV;

    const int n0 = blockIdx.x * 128, o0 = blockIdx.y * 128;
    const int tid = threadIdx.x;
    const int tn = (tid & 15) * 8, to = (tid >> 4) * 8;

    ull acc[8][4];
#pragma unroll
    for (int jj = 0; jj < 8; jj++)
#pragma unroll
        for (int p = 0; p < 4; p++) acc[jj][p] = 0ULL;

    for (int kt = 0; kt < CDIM; kt += 32) {
        __syncthreads();
#pragma unroll
        for (int j = 0; j < 4; j++) {         // W tile: 128x32
            int q = tid + j * 256;            // float4 units
            int r = q >> 3, c4 = (q & 7) * 4;
            float4 w4 = *(const float4*)&Wm[(size_t)(o0 + r) * CDIM + kt + c4];
            Ws[r][c4] = w4.x; Ws[r][c4 + 1] = w4.y;
            Ws[r][c4 + 2] = w4.z; Ws[r][c4 + 3] = w4.w;
        }
#pragma unroll
        for (int j = 0; j < 4; j++) {         // X tile: 32x128
            int q = tid + j * 256;
            int r = q >> 5, c4 = (q & 31) * 4;
            *(float4*)&Xs[r][c4] = *(const float4*)&X[(size_t)(kt + r) * NUMV + n0 + c4];
        }
        __syncthreads();
#pragma unroll
        for (int kk = 0; kk < 32; kk++) {
            ulonglong2 xa = *(const ulonglong2*)&Xs[kk][tn];
            ulonglong2 xb = *(const ulonglong2*)&Xs[kk][tn + 4];
#pragma unroll
            for (int jj = 0; jj < 8; jj++) {
                ull a = dup2(Ws[to + jj][kk]);
                acc[jj][0] = fma2(a, xa.x, acc[jj][0]);
                acc[jj][1] = fma2(a, xa.y, acc[jj][1]);
                acc[jj][2] = fma2(a, xb.x, acc[jj][2]);
                acc[jj][3] = fma2(a, xb.y, acc[jj][3]);
            }
        }
    }
#pragma unroll
    for (int jj = 0; jj < 8; jj++) {
        int og = o0 + to + jj;
        ull bp = dup2(bias[og]);
        float* orow = Out + (size_t)og * NUMV + n0 + tn;
#pragma unroll
        for (int p = 0; p < 4; p++)
            *(ull*)&orow[p * 2] = add2(acc[jj][p], bp);
    }
}

// ========== 2) attention + XLA sigmoid + mask -> score scratch ==============
// 128(o) x 128(i) tile, 256 thr, 8x8 micro, heads sequential ascending
// (matches .sum(axis=1) reduce order); k=32 ascending FMA per head.
__global__ void __launch_bounds__(256)
attn_kernel(const float* __restrict__ H0) {
    __shared__ float Qs[32][128];   // [c][o]
    __shared__ float Ks[32][128];   // [c][i]

    const int b = blockIdx.z;
    const int i0 = blockIdx.x * 128, o0 = blockIdx.y * 128;
    const int tid = threadIdx.x;
    const int ti = (tid & 15) * 8, to = (tid >> 4) * 8;
    const float* Qb = g_Q + (size_t)b * CDIM * NUMV;
    const float* Kb = g_K + (size_t)b * CDIM * NUMV;

    ull sc[8][4];
#pragma unroll
    for (int jj = 0; jj < 8; jj++)
#pragma unroll
        for (int p = 0; p < 4; p++) sc[jj][p] = 0ULL;   // packed (0.f,0.f)

    for (int h = 0; h < NHEAD; h++) {
        __syncthreads();
#pragma unroll
        for (int j = 0; j < 8; j++) {
            int q = tid + j * 256;            // float4 units, 0..2047
            int r = (q >> 5) & 31, c4 = (q & 31) * 4;
            if (q < 1024)
                *(float4*)&Qs[r][c4] = *(const float4*)&Qb[(size_t)(h * 32 + r) * NUMV + o0 + c4];
            else
                *(float4*)&Ks[r][c4] = *(const float4*)&Kb[(size_t)(h * 32 + r) * NUMV + i0 + c4];
        }
        __syncthreads();

        ull acc[8][4];
#pragma unroll
        for (int jj = 0; jj < 8; jj++)
#pragma unroll
            for (int p = 0; p < 4; p++) acc[jj][p] = 0ULL;

#pragma unroll
        for (int kk = 0; kk < 32; kk++) {
            float4 qa = *(const float4*)&Qs[kk][to];
            float4 qc = *(const float4*)&Qs[kk][to + 4];
            ulonglong2 ka = *(const ulonglong2*)&Ks[kk][ti];
            ulonglong2 kb = *(const ulonglong2*)&Ks[kk][ti + 4];
            float qv[8] = {qa.x, qa.y, qa.z, qa.w, qc.x, qc.y, qc.z, qc.w};
#pragma unroll
            for (int jj = 0; jj < 8; jj++) {
                ull a = dup2(qv[jj]);
                acc[jj][0] = fma2(a, ka.x, acc[jj][0]);
                acc[jj][1] = fma2(a, ka.y, acc[jj][1]);
                acc[jj][2] = fma2(a, kb.x, acc[jj][2]);
                acc[jj][3] = fma2(a, kb.y, acc[jj][3]);
            }
        }
        // per-head XLA-replica sigmoid, accumulate ascending h
#pragma unroll
        for (int jj = 0; jj < 8; jj++)
#pragma unroll
            for (int p = 0; p < 4; p++) {
                float x, y; unpack2(acc[jj][p], x, y);
                sc[jj][p] = add2(sc[jj][p], sigmoid_pair(x, y));
            }
    }

    // mask by H0 (masked entries can never reach top-k; force exact 0), /8
    const float* H0b = H0 + (size_t)b * NUMV * NUMV;
    float* Sb = g_S + (size_t)b * NUMV * NUMV;
#pragma unroll
    for (int jj = 0; jj < 8; jj++) {
        size_t rowo = (size_t)(o0 + to + jj) * NUMV + i0 + ti;
        const float* hrow = H0b + rowo;
        float* srow = Sb + rowo;
#pragma unroll
        for (int p = 0; p < 4; p++) {
            float x, y; unpack2(sc[jj][p], x, y);
            float ha = hrow[p * 2], hb = hrow[p * 2 + 1];
            float2 o2;
            o2.x = (ha != 0.0f) ? __fmul_rn(x, 0.125f) : 0.0f;   // /8 exact
            o2.y = (hb != 0.0f) ? __fmul_rn(y, 0.125f) : 0.0f;
            *(float2*)&srow[p * 2] = o2;
        }
    }
}

// ========== 3) exact per-row k-th largest (radix-256 select) + W/H/Dv =======
__device__ __forceinline__ int get_k(const void* iterp) {
    int iv = 1;
    if (iterp) {
        iv = *(const int*)iterp;
        if (iv < 0 || iv > 64) iv = (int)rintf(*(const float*)iterp);
    }
    int k = (int)rintf(2048.0f * 0.1f * (float)(NUM_LAYER - 1 - iv));
    if (k < 1) k = 1;
    if (k > NUMV) k = NUMV;
    return k;
}

__global__ void __launch_bounds__(256)
select_kernel(const void* iterp, float* __restrict__ outH,
              float* __restrict__ outW, float* __restrict__ outDv) {
    __shared__ int hist[256];
    __shared__ unsigned s_prefix;
    __shared__ int s_rem;
    __shared__ int s_cnt[8];

    const int row = blockIdx.x;                       // b*2048 + o
    const float* src = g_S + (size_t)row * NUMV;
    const int tid = threadIdx.x;

    float v[8]; unsigned u[8];
    float4 a0 = *(const float4*)&src[tid * 8];
    float4 a1 = *(const float4*)&src[tid * 8 + 4];
    v[0]=a0.x; v[1]=a0.y; v[2]=a0.z; v[3]=a0.w;
    v[4]=a1.x; v[5]=a1.y; v[6]=a1.z; v[7]=a1.w;
#pragma unroll
    for (int j = 0; j < 8; j++) u[j] = __float_as_uint(v[j]);

    const int k = get_k(iterp);
    unsigned prefix = 0;
    int remaining = k;

#pragma unroll
    for (int pass = 0; pass < 4; pass++) {
        const int shift = 24 - 8 * pass;
        hist[tid] = 0;
        __syncthreads();
#pragma unroll
        for (int j = 0; j < 8; j++) {
            bool act = (pass == 0) ? true : ((u[j] >> (shift + 8)) == prefix);
            if (act) atomicAdd(&hist[(u[j] >> shift) & 255], 1);
        }
        __syncthreads();
        if (tid == 0) {
            int cum = 0;
            unsigned sel = 0; int rem2 = remaining;
            for (int d = 255; d >= 0; d--) {
                int hh = hist[d]; cum += hh;
                if (cum >= remaining) { sel = (unsigned)d; rem2 = remaining - (cum - hh); break; }
            }
            s_prefix = (prefix << 8) | sel;
            s_rem = rem2;
        }
        __syncthreads();
        prefix = s_prefix;
        remaining = s_rem;
    }
    const unsigned T = prefix;   // exact bit pattern of k-th largest value

    int cnt = 0;
    float hh[8], ww[8];
#pragma unroll
    for (int j = 0; j < 8; j++) {
        bool ge = (u[j] >= T);              // score >= a_min (all scores >= 0)
        bool kp = ge && (u[j] != 0u);       // W > 0
        ww[j] = ge ? v[j] : 0.0f;
        hh[j] = kp ? 1.0f : 0.0f;           // H0 is exactly 1.0 where nonzero
        cnt += kp ? 1 : 0;
    }
    size_t ob = (size_t)row * NUMV + tid * 8;
    *(float4*)&outH[ob]     = make_float4(hh[0], hh[1], hh[2], hh[3]);
    *(float4*)&outH[ob + 4] = make_float4(hh[4], hh[5], hh[6], hh[7]);
    *(float4*)&outW[ob]     = make_float4(ww[0], ww[1], ww[2], ww[3]);
    *(float4*)&outW[ob + 4] = make_float4(ww[4], ww[5], ww[6], ww[7]);

    cnt = __reduce_add_sync(0xffffffffu, cnt);
    if ((tid & 31) == 0) s_cnt[tid >> 5] = cnt;
    __syncthreads();
    if (tid == 0) {
        int tot = 0;
#pragma unroll
        for (int w = 0; w < 8; w++) tot += s_cnt[w];
        outDv[row] = __fdiv_rn(1.0f, __fadd_rn((float)tot, 1e-10f));
    }
}

// ========== 4) deterministic column sums -> De, colW ========================
__global__ void __launch_bounds__(512)
colsum_kernel(const float* __restrict__ outH, const float* __restrict__ outW,
              float* __restrict__ outDe) {
    __shared__ float shH[4][128], shW[4][128];
    const int b = blockIdx.y;
    const int c = threadIdx.x & 127;
    const int col = blockIdx.x * 128 + c;
    const int rg = threadIdx.x >> 7;
    const float* Hb = outH + (size_t)b * NUMV * NUMV;
    const float* Wb = outW + (size_t)b * NUMV * NUMV;
    float sh = 0.0f, sw = 0.0f;
    const int r0 = rg * 512;
#pragma unroll 4
    for (int r = r0; r < r0 + 512; r++) {
        size_t idx = (size_t)r * NUMV + col;
        sh += Hb[idx];
        sw += Wb[idx];
    }
    shH[rg][c] = sh; shW[rg][c] = sw;
    __syncthreads();
    if (rg == 0) {
        float th = shH[0][c] + shH[1][c] + shH[2][c] + shH[3][c];  // exact ints
        float tw = shW[0][c] + shW[1][c] + shW[2][c] + shW[3][c];
        outDe[b * NUMV + col] = __fdiv_rn(1.0f, __fadd_rn(th, 1e-10f));
        g_colW[b * NUMV + col] = tw;
    }
}

// ========== 5) per-batch norm of colW -> W_edge =============================
__global__ void __launch_bounds__(512)
finalize_kernel(float* __restrict__ outWe) {
    __shared__ float red[16];
    __shared__ float s_den;
    const int b = blockIdx.x;
    const int tid = threadIdx.x;
    const float* cw = g_colW + b * NUMV;
    float x0 = cw[tid], x1 = cw[tid + 512], x2 = cw[tid + 1024], x3 = cw[tid + 1536];
    float ss = x0 * x0 + x1 * x1 + x2 * x2 + x3 * x3;
#pragma unroll
    for (int off = 16; off >= 1; off >>= 1)
        ss += __shfl_xor_sync(0xffffffffu, ss, off);
    if ((tid & 31) == 0) red[tid >> 5] = ss;
    __syncthreads();
    if (tid == 0) {
        float t = 0.0f;
#pragma unroll
        for (int w = 0; w < 16; w++) t += red[w];
        s_den = fmaxf(__fsqrt_rn(t), 1e-12f);
    }
    __syncthreads();
    float d = s_den;
    outWe[b * NUMV + tid]        = __fdiv_rn(x0, d);
    outWe[b * NUMV + tid + 512]  = __fdiv_rn(x1, d);
    outWe[b * NUMV + tid + 1024] = __fdiv_rn(x2, d);
    outWe[b * NUMV + tid + 1536] = __fdiv_rn(x3, d);
}

// ============================================================================
extern "C" void kernel_launch(void* const* d_in, const int* in_sizes, int n_in,
                              void* d_out, int out_size) {
    const float* H0 = (const float*)d_in[0];
    const float* vf = (const float*)d_in[1];
    const float* ef = (const float*)d_in[2];
    const float* Wq = (const float*)d_in[3];
    const float* bq = (const float*)d_in[4];
    const float* Wk = (const float*)d_in[5];
    const float* bk = (const float*)d_in[6];
    const void* iterp = (n_in >= 8) ? d_in[7] : (const void*)0;

    float* out = (float*)d_out;
    const size_t HW = (size_t)BSZ * NUMV * NUMV;   // 8388608
    float* outH  = out;
    float* outW  = out + HW;
    float* outDe = out + 2 * HW;
    float* outDv = outDe + BSZ * NUMV;
    float* outWe = outDv + BSZ * NUMV;
    (void)in_sizes; (void)out_size;

    proj_kernel<<<dim3(16, 2, 4), 256>>>(vf, ef, Wq, bq, Wk, bk);
    attn_kernel<<<dim3(16, 16, 2), 256>>>(H0);
    select_kernel<<<BSZ * NUMV, 256>>>(iterp, outH, outW, outDv);
    colsum_kernel<<<dim3(16, 2), 512>>>(outH, outW, outDe);
    finalize_kernel<<<BSZ, 512>>>(outWe);
}

// round 12
// speedup vs baseline: 1.3023x; 1.3023x over previous
#include <cuda_runtime.h>
#include <math.h>

typedef unsigned long long ull;

#define NUMV 2048
#define CDIM 256
#define BSZ 2
#define NHEAD 8
#define NUM_LAYER 4

// ---------------- scratch (static device globals; allowed by rules) --------
__device__ float g_Q[BSZ * CDIM * NUMV];                 // 4 MB  [b][c][n]
__device__ float g_K[BSZ * CDIM * NUMV];                 // 4 MB  [b][c][n]
__device__ float g_S[(size_t)BSZ * NUMV * NUMV];         // 33.5 MB score [b][o][i]
__device__ float g_partH[BSZ][8][NUMV];                  // column-sum partials
__device__ float g_partW[BSZ][8][NUMV];

// ---------------- f32x2 helpers (Blackwell packed fp32, RN rounding) --------
__device__ __forceinline__ ull dup2(float x) {
    ull d; unsigned u = __float_as_uint(x);
    asm("mov.b64 %0, {%1, %1};" : "=l"(d) : "r"(u));
    return d;
}
__device__ __forceinline__ ull pack2(float x, float y) {
    ull d;
    asm("mov.b64 %0, {%1, %2};" : "=l"(d)
        : "r"(__float_as_uint(x)), "r"(__float_as_uint(y)));
    return d;
}
__device__ __forceinline__ ull fma2(ull a, ull b, ull c) {
    ull d; asm("fma.rn.f32x2 %0, %1, %2, %3;" : "=l"(d) : "l"(a), "l"(b), "l"(c));
    return d;
}
__device__ __forceinline__ ull add2(ull a, ull b) {
    ull d; asm("add.rn.f32x2 %0, %1, %2;" : "=l"(d) : "l"(a), "l"(b));
    return d;
}
__device__ __forceinline__ ull mul2(ull a, ull b) {
    ull d; asm("mul.rn.f32x2 %0, %1, %2;" : "=l"(d) : "l"(a), "l"(b));
    return d;
}
__device__ __forceinline__ void unpack2(ull v, float &x, float &y) {
    unsigned lo, hi;
    asm("mov.b64 {%0, %1}, %2;" : "=r"(lo), "=r"(hi) : "l"(v));
    x = __uint_as_float(lo); y = __uint_as_float(hi);
}

// ---------------- XLA-replica sigmoid (bit-preserving fast version) --------
// Reference chain: x = attn / f32(sqrt32); logistic = 0.5 + 0.5*fast_tanh(0.5x)
// fast_tanh = XLA EmitFastTanh rational poly, RN throughout.
// Optimizations (all provably identical rounding):
//  * 0.5*(a/c) == RN(a/(2c)); division by constant 2c via Markstein (3 ops).
//  * num/den division replicates ptxas div.rn.f32 fast path (rcp.approx +
//    Newton + Markstein correction), packed f32x2.
__device__ __forceinline__ ull sigmoid_pair(ull a) {
    const float C2 = 11.313708498984760390f;      // exactly 2 * f32(sqrt(32))
    const float R2s = __frcp_rn(C2);              // RN(1/C2)  (loop-invariant)
    const ull r2 = dup2(R2s), nc2 = dup2(-C2);
    // h = RN(a / C2)  == 0.5 * RN(a / sqrt32)  bit-exactly
    ull q0 = mul2(a, r2);
    ull ee = fma2(nc2, q0, a);
    ull h  = fma2(ee, r2, q0);
    float h0, h1; unpack2(h, h0, h1);
    float c0 = fminf(fmaxf(h0, -9.0f), 9.0f);
    float c1 = fminf(fmaxf(h1, -9.0f), 9.0f);
    ull cc = pack2(c0, c1);
    ull x2 = mul2(cc, cc);
    // numerator Horner (separate mul/add, RN)
    ull p = dup2(-2.76076847742355e-16f);
    p = add2(mul2(p, x2), dup2( 2.00018790482477e-13f));
    p = add2(mul2(p, x2), dup2(-8.60467152213735e-11f));
    p = add2(mul2(p, x2), dup2( 5.12229709037114e-08f));
    p = add2(mul2(p, x2), dup2( 1.48572235717979e-05f));
    p = add2(mul2(p, x2), dup2( 6.37261928875436e-04f));
    p = add2(mul2(p, x2), dup2( 4.89352455891786e-03f));
    ull num = mul2(cc, p);
    // denominator Horner
    ull q = dup2(1.19825839466702e-06f);
    q = add2(mul2(q, x2), dup2(1.18534705686654e-04f));
    q = add2(mul2(q, x2), dup2(2.26843463243900e-03f));
    q = add2(mul2(q, x2), dup2(4.89352518554385e-03f));
    // packed correctly-rounded num/q (div.rn.f32 fast-path replica)
    float d0, d1; unpack2(q, d0, d1);
    float ra, rb;
    asm("rcp.approx.f32 %0, %1;" : "=f"(ra) : "f"(d0));
    asm("rcp.approx.f32 %0, %1;" : "=f"(rb) : "f"(d1));
    ull r  = pack2(ra, rb);
    ull nd = q ^ 0x8000000080000000ULL;          // -den (finite, safe)
    ull one2 = dup2(1.0f);
    ull t1 = fma2(nd, r, one2);
    ull r1 = fma2(t1, r, r);                      // refined reciprocal
    ull qq = mul2(num, r1);
    ull e2 = fma2(nd, qq, num);
    ull t  = fma2(e2, r1, qq);                    // RN(num/den)
    float t0, t1f; unpack2(t, t0, t1f);
    if (fabsf(h0) < 0.0004f) t0 = h0;             // XLA small-x fallback
    if (fabsf(h1) < 0.0004f) t1f = h1;
    // s = 0.5 + 0.5*t  (0.5*t exact -> single fma identical)
    ull half = dup2(0.5f);
    return fma2(half, pack2(t0, t1f), half);
}

// ======================= 1) projections =====================================
// Out[b][o][n] = W @ X + bias.  Sequential ascending-k fp32 FMA chain.
__global__ void __launch_bounds__(256)
proj_kernel(const float* __restrict__ vf, const float* __restrict__ ef,
            const float* __restrict__ Wq, const float* __restrict__ bq,
            const float* __restrict__ Wk, const float* __restrict__ bk) {
    __shared__ float Ws[128][33];   // [o][c] padded
    __shared__ float Xs[32][128];   // [c][n]

    const int zb = blockIdx.z;
    const int b = zb & 1, which = zb >> 1;
    const float* X    = (which ? ef : vf) + (size_t)b * CDIM * NUMV;
    const float* Wm   = which ? Wk : Wq;
    const float* bias = which ? bk : bq;
    float* Out = (which ? g_K : g_Q) + (size_t)b * CDIM * NUMV;

    const int n0 = blockIdx.x * 128, o0 = blockIdx.y * 128;
    const int tid = threadIdx.x;
    const int tn = (tid & 15) * 8, to = (tid >> 4) * 8;

    ull acc[8][4];
#pragma unroll
    for (int jj = 0; jj < 8; jj++)
#pragma unroll
        for (int p = 0; p < 4; p++) acc[jj][p] = 0ULL;

    for (int kt = 0; kt < CDIM; kt += 32) {
        __syncthreads();
#pragma unroll
        for (int j = 0; j < 4; j++) {         // W tile: 128x32
            int q = tid + j * 256;            // float4 units
            int r = q >> 3, c4 = (q & 7) * 4;
            float4 w4 = *(const float4*)&Wm[(size_t)(o0 + r) * CDIM + kt + c4];
            Ws[r][c4] = w4.x; Ws[r][c4 + 1] = w4.y;
            Ws[r][c4 + 2] = w4.z; Ws[r][c4 + 3] = w4.w;
        }
#pragma unroll
        for (int j = 0; j < 4; j++) {         // X tile: 32x128
            int q = tid + j * 256;
            int r = q >> 5, c4 = (q & 31) * 4;
            *(float4*)&Xs[r][c4] = *(const float4*)&X[(size_t)(kt + r) * NUMV + n0 + c4];
        }
        __syncthreads();
#pragma unroll
        for (int kk = 0; kk < 32; kk++) {
            ulonglong2 xa = *(const ulonglong2*)&Xs[kk][tn];
            ulonglong2 xb = *(const ulonglong2*)&Xs[kk][tn + 4];
#pragma unroll
            for (int jj = 0; jj < 8; jj++) {
                ull a = dup2(Ws[to + jj][kk]);
                acc[jj][0] = fma2(a, xa.x, acc[jj][0]);
                acc[jj][1] = fma2(a, xa.y, acc[jj][1]);
                acc[jj][2] = fma2(a, xb.x, acc[jj][2]);
                acc[jj][3] = fma2(a, xb.y, acc[jj][3]);
            }
        }
    }
#pragma unroll
    for (int jj = 0; jj < 8; jj++) {
        int og = o0 + to + jj;
        ull bp = dup2(bias[og]);
        float* orow = Out + (size_t)og * NUMV + n0 + tn;
#pragma unroll
        for (int p = 0; p < 4; p++)
            *(ull*)&orow[p * 2] = add2(acc[jj][p], bp);
    }
}

// ========== 2) attention + XLA sigmoid + mask -> score scratch ==============
__global__ void __launch_bounds__(256)
attn_kernel(const float* __restrict__ H0) {
    __shared__ float Qs[32][128];   // [c][o]
    __shared__ float Ks[32][128];   // [c][i]

    const int b = blockIdx.z;
    const int i0 = blockIdx.x * 128, o0 = blockIdx.y * 128;
    const int tid = threadIdx.x;
    const int ti = (tid & 15) * 8, to = (tid >> 4) * 8;
    const float* Qb = g_Q + (size_t)b * CDIM * NUMV;
    const float* Kb = g_K + (size_t)b * CDIM * NUMV;

    ull sc[8][4];
#pragma unroll
    for (int jj = 0; jj < 8; jj++)
#pragma unroll
        for (int p = 0; p < 4; p++) sc[jj][p] = 0ULL;   // packed (0.f,0.f)

    for (int h = 0; h < NHEAD; h++) {
        __syncthreads();
#pragma unroll
        for (int j = 0; j < 8; j++) {
            int q = tid + j * 256;            // float4 units, 0..2047
            int r = (q >> 5) & 31, c4 = (q & 31) * 4;
            if (q < 1024)
                *(float4*)&Qs[r][c4] = *(const float4*)&Qb[(size_t)(h * 32 + r) * NUMV + o0 + c4];
            else
                *(float4*)&Ks[r][c4] = *(const float4*)&Kb[(size_t)(h * 32 + r) * NUMV + i0 + c4];
        }
        __syncthreads();

        ull acc[8][4];
#pragma unroll
        for (int jj = 0; jj < 8; jj++)
#pragma unroll
            for (int p = 0; p < 4; p++) acc[jj][p] = 0ULL;

#pragma unroll
        for (int kk = 0; kk < 32; kk++) {
            float4 qa = *(const float4*)&Qs[kk][to];
            float4 qc = *(const float4*)&Qs[kk][to + 4];
            ulonglong2 ka = *(const ulonglong2*)&Ks[kk][ti];
            ulonglong2 kb = *(const ulonglong2*)&Ks[kk][ti + 4];
            float qv[8] = {qa.x, qa.y, qa.z, qa.w, qc.x, qc.y, qc.z, qc.w};
#pragma unroll
            for (int jj = 0; jj < 8; jj++) {
                ull a = dup2(qv[jj]);
                acc[jj][0] = fma2(a, ka.x, acc[jj][0]);
                acc[jj][1] = fma2(a, ka.y, acc[jj][1]);
                acc[jj][2] = fma2(a, kb.x, acc[jj][2]);
                acc[jj][3] = fma2(a, kb.y, acc[jj][3]);
            }
        }
        // per-head XLA-replica sigmoid, accumulate ascending h
#pragma unroll
        for (int jj = 0; jj < 8; jj++)
#pragma unroll
            for (int p = 0; p < 4; p++)
                sc[jj][p] = add2(sc[jj][p], sigmoid_pair(acc[jj][p]));
    }

    // mask by H0 (masked entries can never reach top-k; force exact 0), /8
    const float* H0b = H0 + (size_t)b * NUMV * NUMV;
    float* Sb = g_S + (size_t)b * NUMV * NUMV;
#pragma unroll
    for (int jj = 0; jj < 8; jj++) {
        size_t rowo = (size_t)(o0 + to + jj) * NUMV + i0 + ti;
        const float* hrow = H0b + rowo;
        float* srow = Sb + rowo;
#pragma unroll
        for (int p = 0; p < 4; p++) {
            float x, y; unpack2(sc[jj][p], x, y);
            float ha = hrow[p * 2], hb = hrow[p * 2 + 1];
            float2 o2;
            o2.x = (ha != 0.0f) ? __fmul_rn(x, 0.125f) : 0.0f;   // /8 exact
            o2.y = (hb != 0.0f) ? __fmul_rn(y, 0.125f) : 0.0f;
            *(float2*)&srow[p * 2] = o2;
        }
    }
}

// ========== 3) exact per-row k-th largest (radix-256 select) + W/H/Dv =======
__device__ __forceinline__ int get_k(const void* iterp) {
    int iv = 1;
    if (iterp) {
        iv = *(const int*)iterp;
        if (iv < 0 || iv > 64) iv = (int)rintf(*(const float*)iterp);
    }
    int k = (int)rintf(2048.0f * 0.1f * (float)(NUM_LAYER - 1 - iv));
    if (k < 1) k = 1;
    if (k > NUMV) k = NUMV;
    return k;
}

__global__ void __launch_bounds__(256)
select_kernel(const void* iterp, float* __restrict__ outH,
              float* __restrict__ outW, float* __restrict__ outDv) {
    __shared__ int hist[256];
    __shared__ unsigned s_prefix;
    __shared__ int s_rem;
    __shared__ int s_cnt[8];

    const int row = blockIdx.x;                       // b*2048 + o
    const float* src = g_S + (size_t)row * NUMV;
    const int tid = threadIdx.x;

    float v[8]; unsigned u[8];
    float4 a0 = *(const float4*)&src[tid * 8];
    float4 a1 = *(const float4*)&src[tid * 8 + 4];
    v[0]=a0.x; v[1]=a0.y; v[2]=a0.z; v[3]=a0.w;
    v[4]=a1.x; v[5]=a1.y; v[6]=a1.z; v[7]=a1.w;
#pragma unroll
    for (int j = 0; j < 8; j++) u[j] = __float_as_uint(v[j]);

    const int k = get_k(iterp);
    unsigned prefix = 0;
    int remaining = k;

#pragma unroll
    for (int pass = 0; pass < 4; pass++) {
        const int shift = 24 - 8 * pass;
        hist[tid] = 0;
        __syncthreads();
#pragma unroll
        for (int j = 0; j < 8; j++) {
            bool act = (pass == 0) ? true : ((u[j] >> (shift + 8)) == prefix);
            if (act) atomicAdd(&hist[(u[j] >> shift) & 255], 1);
        }
        __syncthreads();
        if (tid == 0) {
            int cum = 0;
            unsigned sel = 0; int rem2 = remaining;
            for (int d = 255; d >= 0; d--) {
                int hh = hist[d]; cum += hh;
                if (cum >= remaining) { sel = (unsigned)d; rem2 = remaining - (cum - hh); break; }
            }
            s_prefix = (prefix << 8) | sel;
            s_rem = rem2;
        }
        __syncthreads();
        prefix = s_prefix;
        remaining = s_rem;
    }
    const unsigned T = prefix;   // exact bit pattern of k-th largest value

    int cnt = 0;
    float hh[8], ww[8];
#pragma unroll
    for (int j = 0; j < 8; j++) {
        bool ge = (u[j] >= T);              // score >= a_min (all scores >= 0)
        bool kp = ge && (u[j] != 0u);       // W > 0
        ww[j] = ge ? v[j] : 0.0f;
        hh[j] = kp ? 1.0f : 0.0f;           // H0 is exactly 1.0 where nonzero
        cnt += kp ? 1 : 0;
    }
    size_t ob = (size_t)row * NUMV + tid * 8;
    *(float4*)&outH[ob]     = make_float4(hh[0], hh[1], hh[2], hh[3]);
    *(float4*)&outH[ob + 4] = make_float4(hh[4], hh[5], hh[6], hh[7]);
    *(float4*)&outW[ob]     = make_float4(ww[0], ww[1], ww[2], ww[3]);
    *(float4*)&outW[ob + 4] = make_float4(ww[4], ww[5], ww[6], ww[7]);

    cnt = __reduce_add_sync(0xffffffffu, cnt);
    if ((tid & 31) == 0) s_cnt[tid >> 5] = cnt;
    __syncthreads();
    if (tid == 0) {
        int tot = 0;
#pragma unroll
        for (int w = 0; w < 8; w++) tot += s_cnt[w];
        outDv[row] = __fdiv_rn(1.0f, __fadd_rn((float)tot, 1e-10f));
    }
}

// ========== 4a) column-sum partials (256 CTAs, streaming) ===================
__global__ void __launch_bounds__(256)
colsumA_kernel(const float* __restrict__ outH, const float* __restrict__ outW) {
    __shared__ float sH[2][128], sW[2][128];
    const int b = blockIdx.z;
    const int c = threadIdx.x & 127;
    const int col = blockIdx.x * 128 + c;
    const int half = threadIdx.x >> 7;
    const int r0 = blockIdx.y * 256 + half * 128;
    const float* Hb = outH + (size_t)b * NUMV * NUMV;
    const float* Wb = outW + (size_t)b * NUMV * NUMV;
    float sh = 0.0f, sw = 0.0f;
#pragma unroll 4
    for (int r = r0; r < r0 + 128; r++) {
        size_t idx = (size_t)r * NUMV + col;
        sh += Hb[idx];
        sw += Wb[idx];
    }
    sH[half][c] = sh; sW[half][c] = sw;
    __syncthreads();
    if (half == 0) {
        g_partH[b][blockIdx.y][col] = sH[0][c] + sH[1][c];
        g_partW[b][blockIdx.y][col] = sW[0][c] + sW[1][c];
    }
}

// ========== 4b) reduce partials -> De, colW; norm -> W_edge =================
__global__ void __launch_bounds__(512)
finalize_kernel(float* __restrict__ outDe, float* __restrict__ outWe) {
    __shared__ float red[16];
    __shared__ float s_den;
    const int b = blockIdx.x;
    const int tid = threadIdx.x;

    float cw[4];
    float ss = 0.0f;
#pragma unroll
    for (int j = 0; j < 4; j++) {
        int col = tid + j * 512;
        float th = 0.0f, tw = 0.0f;
#pragma unroll
        for (int ch = 0; ch < 8; ch++) {
            th += g_partH[b][ch][col];   // exact integers: order-free
            tw += g_partW[b][ch][col];
        }
        outDe[b * NUMV + col] = __fdiv_rn(1.0f, __fadd_rn(th, 1e-10f));
        cw[j] = tw;
        ss += tw * tw;
    }
#pragma unroll
    for (int off = 16; off >= 1; off >>= 1)
        ss += __shfl_xor_sync(0xffffffffu, ss, off);
    if ((tid & 31) == 0) red[tid >> 5] = ss;
    __syncthreads();
    if (tid == 0) {
        float t = 0.0f;
#pragma unroll
        for (int w = 0; w < 16; w++) t += red[w];
        s_den = fmaxf(__fsqrt_rn(t), 1e-12f);
    }
    __syncthreads();
    float d = s_den;
#pragma unroll
    for (int j = 0; j < 4; j++)
        outWe[b * NUMV + tid + j * 512] = __fdiv_rn(cw[j], d);
}

// ============================================================================
extern "C" void kernel_launch(void* const* d_in, const int* in_sizes, int n_in,
                              void* d_out, int out_size) {
    const float* H0 = (const float*)d_in[0];
    const float* vf = (const float*)d_in[1];
    const float* ef = (const float*)d_in[2];
    const float* Wq = (const float*)d_in[3];
    const float* bq = (const float*)d_in[4];
    const float* Wk = (const float*)d_in[5];
    const float* bk = (const float*)d_in[6];
    const void* iterp = (n_in >= 8) ? d_in[7] : (const void*)0;

    float* out = (float*)d_out;
    const size_t HW = (size_t)BSZ * NUMV * NUMV;   // 8388608
    float* outH  = out;
    float* outW  = out + HW;
    float* outDe = out + 2 * HW;
    float* outDv = outDe + BSZ * NUMV;
    float* outWe = outDv + BSZ * NUMV;
    (void)in_sizes; (void)out_size;

    proj_kernel<<<dim3(16, 2, 4), 256>>>(vf, ef, Wq, bq, Wk, bk);
    attn_kernel<<<dim3(16, 16, 2), 256>>>(H0);
    select_kernel<<<BSZ * NUMV, 256>>>(iterp, outH, outW, outDv);
    colsumA_kernel<<<dim3(16, 8, 2), 256>>>(outH, outW);
    finalize_kernel<<<BSZ, 512>>>(outDe, outWe);
}

// round 15
// speedup vs baseline: 1.9217x; 1.4757x over previous
#include <cuda_runtime.h>
#include <math.h>

typedef unsigned long long ull;

#define NUMV 2048
#define CDIM 256
#define BSZ 2
#define NHEAD 8
#define NUM_LAYER 4

// ---------------- scratch (static device globals; allowed by rules) --------
__device__ float g_Q[BSZ * CDIM * NUMV];                 // 4 MB  [b][c][n]
__device__ float g_K[BSZ * CDIM * NUMV];                 // 4 MB  [b][c][n]
__device__ float g_S[(size_t)BSZ * NUMV * NUMV];         // 33.5 MB score [b][o][i]
__device__ float g_partH[BSZ][32][NUMV];                 // column-sum partials
__device__ float g_partW[BSZ][32][NUMV];

// ---------------- f32x2 helpers (Blackwell packed fp32, RN rounding) --------
__device__ __forceinline__ ull dup2(float x) {
    ull d; unsigned u = __float_as_uint(x);
    asm("mov.b64 %0, {%1, %1};" : "=l"(d) : "r"(u));
    return d;
}
__device__ __forceinline__ ull pack2(float x, float y) {
    ull d;
    asm("mov.b64 %0, {%1, %2};" : "=l"(d)
        : "r"(__float_as_uint(x)), "r"(__float_as_uint(y)));
    return d;
}
__device__ __forceinline__ ull fma2(ull a, ull b, ull c) {
    ull d; asm("fma.rn.f32x2 %0, %1, %2, %3;" : "=l"(d) : "l"(a), "l"(b), "l"(c));
    return d;
}
__device__ __forceinline__ ull add2(ull a, ull b) {
    ull d; asm("add.rn.f32x2 %0, %1, %2;" : "=l"(d) : "l"(a), "l"(b));
    return d;
}
__device__ __forceinline__ ull mul2(ull a, ull b) {
    ull d; asm("mul.rn.f32x2 %0, %1, %2;" : "=l"(d) : "l"(a), "l"(b));
    return d;
}
__device__ __forceinline__ void unpack2(ull v, float &x, float &y) {
    unsigned lo, hi;
    asm("mov.b64 {%0, %1}, %2;" : "=r"(lo), "=r"(hi) : "l"(v));
    x = __uint_as_float(lo); y = __uint_as_float(hi);
}

// ---------------- XLA-replica sigmoid (bit-preserving fast version) --------
// Reference chain: x = attn / f32(sqrt32); logistic = 0.5 + 0.5*fast_tanh(0.5x)
// fast_tanh = XLA EmitFastTanh rational poly, RN throughout.
//  * 0.5*(a/c) == RN(a/(2c)); division by constant 2c via Markstein (3 ops).
//  * num/den division replicates ptxas div.rn.f32 fast path, packed f32x2.
__device__ __forceinline__ ull sigmoid_pair(ull a) {
    const float C2 = 11.313708498984760390f;      // exactly 2 * f32(sqrt(32))
    const float R2s = __frcp_rn(C2);              // RN(1/C2)  (loop-invariant)
    const ull r2 = dup2(R2s), nc2 = dup2(-C2);
    // h = RN(a / C2)  == 0.5 * RN(a / sqrt32)  bit-exactly
    ull q0 = mul2(a, r2);
    ull ee = fma2(nc2, q0, a);
    ull h  = fma2(ee, r2, q0);
    float h0, h1; unpack2(h, h0, h1);
    float c0 = fminf(fmaxf(h0, -9.0f), 9.0f);
    float c1 = fminf(fmaxf(h1, -9.0f), 9.0f);
    ull cc = pack2(c0, c1);
    ull x2 = mul2(cc, cc);
    // numerator Horner (separate mul/add, RN)
    ull p = dup2(-2.76076847742355e-16f);
    p = add2(mul2(p, x2), dup2( 2.00018790482477e-13f));
    p = add2(mul2(p, x2), dup2(-8.60467152213735e-11f));
    p = add2(mul2(p, x2), dup2( 5.12229709037114e-08f));
    p = add2(mul2(p, x2), dup2( 1.48572235717979e-05f));
    p = add2(mul2(p, x2), dup2( 6.37261928875436e-04f));
    p = add2(mul2(p, x2), dup2( 4.89352455891786e-03f));
    ull num = mul2(cc, p);
    // denominator Horner
    ull q = dup2(1.19825839466702e-06f);
    q = add2(mul2(q, x2), dup2(1.18534705686654e-04f));
    q = add2(mul2(q, x2), dup2(2.26843463243900e-03f));
    q = add2(mul2(q, x2), dup2(4.89352518554385e-03f));
    // packed correctly-rounded num/q (div.rn.f32 fast-path replica)
    float d0, d1; unpack2(q, d0, d1);
    float ra, rb;
    asm("rcp.approx.f32 %0, %1;" : "=f"(ra) : "f"(d0));
    asm("rcp.approx.f32 %0, %1;" : "=f"(rb) : "f"(d1));
    ull r  = pack2(ra, rb);
    ull nd = q ^ 0x8000000080000000ULL;          // -den (finite, safe)
    ull one2 = dup2(1.0f);
    ull t1 = fma2(nd, r, one2);
    ull r1 = fma2(t1, r, r);                      // refined reciprocal
    ull qq = mul2(num, r1);
    ull e2 = fma2(nd, qq, num);
    ull t  = fma2(e2, r1, qq);                    // RN(num/den)
    float t0, t1f; unpack2(t, t0, t1f);
    if (fabsf(h0) < 0.0004f) t0 = h0;             // XLA small-x fallback
    if (fabsf(h1) < 0.0004f) t1f = h1;
    // s = 0.5 + 0.5*t  (0.5*t exact -> single fma identical)
    ull half = dup2(0.5f);
    return fma2(half, pack2(t0, t1f), half);
}

// ======================= 1) projections =====================================
// Out[b][o][n] = W @ X + bias.  Sequential ascending-k fp32 FMA chain.
__global__ void __launch_bounds__(256)
proj_kernel(const float* __restrict__ vf, const float* __restrict__ ef,
            const float* __restrict__ Wq, const float* __restrict__ bq,
            const float* __restrict__ Wk, const float* __restrict__ bk) {
    __shared__ float Ws[128][33];   // [o][c] padded
    __shared__ float Xs[32][128];   // [c][n]

    const int zb = blockIdx.z;
    const int b = zb & 1, which = zb >> 1;
    const float* X    = (which ? ef : vf) + (size_t)b * CDIM * NUMV;
    const float* Wm   = which ? Wk : Wq;
    const float* bias = which ? bk : bq;
    float* Out = (which ? g_K : g_Q) + (size_t)b * CDIM * NUMV;

    const int n0 = blockIdx.x * 128, o0 = blockIdx.y * 128;
    const int tid = threadIdx.x;
    const int tn = (tid & 15) * 8, to = (tid >> 4) * 8;

    ull acc[8][4];
#pragma unroll
    for (int jj = 0; jj < 8; jj++)
#pragma unroll
        for (int p = 0; p < 4; p++) acc[jj][p] = 0ULL;

    for (int kt = 0; kt < CDIM; kt += 32) {
        __syncthreads();
#pragma unroll
        for (int j = 0; j < 4; j++) {         // W tile: 128x32
            int q = tid + j * 256;            // float4 units
            int r = q >> 3, c4 = (q & 7) * 4;
            float4 w4 = *(const float4*)&Wm[(size_t)(o0 + r) * CDIM + kt + c4];
            Ws[r][c4] = w4.x; Ws[r][c4 + 1] = w4.y;
            Ws[r][c4 + 2] = w4.z; Ws[r][c4 + 3] = w4.w;
        }
#pragma unroll
        for (int j = 0; j < 4; j++) {         // X tile: 32x128
            int q = tid + j * 256;
            int r = q >> 5, c4 = (q & 31) * 4;
            *(float4*)&Xs[r][c4] = *(const float4*)&X[(size_t)(kt + r) * NUMV + n0 + c4];
        }
        __syncthreads();
#pragma unroll
        for (int kk = 0; kk < 32; kk++) {
            ulonglong2 xa = *(const ulonglong2*)&Xs[kk][tn];
            ulonglong2 xb = *(const ulonglong2*)&Xs[kk][tn + 4];
#pragma unroll
            for (int jj = 0; jj < 8; jj++) {
                ull a = dup2(Ws[to + jj][kk]);
                acc[jj][0] = fma2(a, xa.x, acc[jj][0]);
                acc[jj][1] = fma2(a, xa.y, acc[jj][1]);
                acc[jj][2] = fma2(a, xb.x, acc[jj][2]);
                acc[jj][3] = fma2(a, xb.y, acc[jj][3]);
            }
        }
    }
#pragma unroll
    for (int jj = 0; jj < 8; jj++) {
        int og = o0 + to + jj;
        ull bp = dup2(bias[og]);
        float* orow = Out + (size_t)og * NUMV + n0 + tn;
#pragma unroll
        for (int p = 0; p < 4; p++)
            *(ull*)&orow[p * 2] = add2(acc[jj][p], bp);
    }
}

// ========== 2) attention + XLA sigmoid + mask -> score scratch ==============
// 128(o) x 64(i) tile (1024 CTAs: kills wave quantization, halves regs),
// 256 thr, micro 8(o) x 4(i). Identical per-element arithmetic as before.
__global__ void __launch_bounds__(256)
attn_kernel(const float* __restrict__ H0) {
    __shared__ float Qs[32][128];   // [c][o]
    __shared__ float Ks[32][64];    // [c][i]

    const int b = blockIdx.z;
    const int i0 = blockIdx.x * 64, o0 = blockIdx.y * 128;
    const int tid = threadIdx.x;
    const int ti = (tid & 15) * 4, to = (tid >> 4) * 8;
    const float* Qb = g_Q + (size_t)b * CDIM * NUMV;
    const float* Kb = g_K + (size_t)b * CDIM * NUMV;

    ull sc[8][2];
#pragma unroll
    for (int jj = 0; jj < 8; jj++) { sc[jj][0] = 0ULL; sc[jj][1] = 0ULL; }

    for (int h = 0; h < NHEAD; h++) {
        __syncthreads();
#pragma unroll
        for (int j = 0; j < 4; j++) {         // Q tile: 32x128 = 1024 float4
            int q = tid + j * 256;
            int r = q >> 5, c4 = (q & 31) * 4;
            *(float4*)&Qs[r][c4] = *(const float4*)&Qb[(size_t)(h * 32 + r) * NUMV + o0 + c4];
        }
#pragma unroll
        for (int j = 0; j < 2; j++) {         // K tile: 32x64 = 512 float4
            int q = tid + j * 256;
            int r = q >> 4, c4 = (q & 15) * 4;
            *(float4*)&Ks[r][c4] = *(const float4*)&Kb[(size_t)(h * 32 + r) * NUMV + i0 + c4];
        }
        __syncthreads();

        ull acc[8][2];
#pragma unroll
        for (int jj = 0; jj < 8; jj++) { acc[jj][0] = 0ULL; acc[jj][1] = 0ULL; }

#pragma unroll
        for (int kk = 0; kk < 32; kk++) {
            float4 qa = *(const float4*)&Qs[kk][to];
            float4 qc = *(const float4*)&Qs[kk][to + 4];
            ulonglong2 kp = *(const ulonglong2*)&Ks[kk][ti];
            float qv[8] = {qa.x, qa.y, qa.z, qa.w, qc.x, qc.y, qc.z, qc.w};
#pragma unroll
            for (int jj = 0; jj < 8; jj++) {
                ull a = dup2(qv[jj]);
                acc[jj][0] = fma2(a, kp.x, acc[jj][0]);
                acc[jj][1] = fma2(a, kp.y, acc[jj][1]);
            }
        }
        // per-head XLA-replica sigmoid, accumulate ascending h
#pragma unroll
        for (int jj = 0; jj < 8; jj++) {
            sc[jj][0] = add2(sc[jj][0], sigmoid_pair(acc[jj][0]));
            sc[jj][1] = add2(sc[jj][1], sigmoid_pair(acc[jj][1]));
        }
    }

    // mask by H0 (masked entries can never reach top-k; force exact 0), /8
    const float* H0b = H0 + (size_t)b * NUMV * NUMV;
    float* Sb = g_S + (size_t)b * NUMV * NUMV;
#pragma unroll
    for (int jj = 0; jj < 8; jj++) {
        size_t rowo = (size_t)(o0 + to + jj) * NUMV + i0 + ti;
        float4 hv = *(const float4*)&H0b[rowo];
        float x0, x1, x2c, x3; 
        unpack2(sc[jj][0], x0, x1);
        unpack2(sc[jj][1], x2c, x3);
        float4 o4;
        o4.x = (hv.x != 0.0f) ? __fmul_rn(x0, 0.125f) : 0.0f;   // /8 exact
        o4.y = (hv.y != 0.0f) ? __fmul_rn(x1, 0.125f) : 0.0f;
        o4.z = (hv.z != 0.0f) ? __fmul_rn(x2c, 0.125f) : 0.0f;
        o4.w = (hv.w != 0.0f) ? __fmul_rn(x3, 0.125f) : 0.0f;
        *(float4*)&Sb[rowo] = o4;
    }
}

// ========== 3) exact per-row k-th largest (radix-256 select) + W/H/Dv =======
__device__ __forceinline__ int get_k(const void* iterp) {
    int iv = 1;
    if (iterp) {
        iv = *(const int*)iterp;
        if (iv < 0 || iv > 64) iv = (int)rintf(*(const float*)iterp);
    }
    int k = (int)rintf(2048.0f * 0.1f * (float)(NUM_LAYER - 1 - iv));
    if (k < 1) k = 1;
    if (k > NUMV) k = NUMV;
    return k;
}

__global__ void __launch_bounds__(256)
select_kernel(const void* iterp, float* __restrict__ outH,
              float* __restrict__ outW, float* __restrict__ outDv) {
    __shared__ int hist[256];
    __shared__ int warpTot[8];
    __shared__ unsigned s_prefix;
    __shared__ int s_rem;
    __shared__ int s_cnt[8];

    const int row = blockIdx.x;                       // b*2048 + o
    const float* src = g_S + (size_t)row * NUMV;
    const int tid = threadIdx.x;
    const int lane = tid & 31, wid = tid >> 5;

    float v[8]; unsigned u[8];
    float4 a0 = *(const float4*)&src[tid * 8];
    float4 a1 = *(const float4*)&src[tid * 8 + 4];
    v[0]=a0.x; v[1]=a0.y; v[2]=a0.z; v[3]=a0.w;
    v[4]=a1.x; v[5]=a1.y; v[6]=a1.z; v[7]=a1.w;
#pragma unroll
    for (int j = 0; j < 8; j++) u[j] = __float_as_uint(v[j]);

    const int k = get_k(iterp);
    unsigned prefix = 0;
    int remaining = k;

#pragma unroll
    for (int pass = 0; pass < 4; pass++) {
        const int shift = 24 - 8 * pass;
        hist[tid] = 0;
        __syncthreads();
#pragma unroll
        for (int j = 0; j < 8; j++) {
            bool act = (pass == 0) ? true : ((u[j] >> (shift + 8)) == prefix);
            if (act) atomicAdd(&hist[(u[j] >> shift) & 255], 1);
        }
        __syncthreads();
        // parallel suffix scan over 256 bins (replaces tid-0 serial loop)
        int sv = hist[tid];
#pragma unroll
        for (int off = 1; off < 32; off <<= 1) {
            int t = __shfl_down_sync(0xffffffffu, sv, off);
            if (lane < 32 - off) sv += t;
        }
        if (lane == 0) warpTot[wid] = sv;   // warp's bin-range total
        __syncthreads();
        int off_w = 0;
#pragma unroll
        for (int w = 0; w < 8; w++)
            if (w > wid) off_w += warpTot[w];
        int suf = sv + off_w;               // inclusive suffix sum at bin tid
        int sufNext = __shfl_down_sync(0xffffffffu, suf, 1);
        if (lane == 31) sufNext = off_w;    // first bin of next warp (or 0)
        if (suf >= remaining && sufNext < remaining) {
            s_prefix = (prefix << 8) | (unsigned)tid;
            s_rem = remaining - sufNext;
        }
        __syncthreads();
        prefix = s_prefix;
        remaining = s_rem;
    }
    const unsigned T = prefix;   // exact bit pattern of k-th largest value

    int cnt = 0;
    float hh[8], ww[8];
#pragma unroll
    for (int j = 0; j < 8; j++) {
        bool ge = (u[j] >= T);              // score >= a_min (all scores >= 0)
        bool kp = ge && (u[j] != 0u);       // W > 0
        ww[j] = ge ? v[j] : 0.0f;
        hh[j] = kp ? 1.0f : 0.0f;           // H0 is exactly 1.0 where nonzero
        cnt += kp ? 1 : 0;
    }
    size_t ob = (size_t)row * NUMV + tid * 8;
    *(float4*)&outH[ob]     = make_float4(hh[0], hh[1], hh[2], hh[3]);
    *(float4*)&outH[ob + 4] = make_float4(hh[4], hh[5], hh[6], hh[7]);
    *(float4*)&outW[ob]     = make_float4(ww[0], ww[1], ww[2], ww[3]);
    *(float4*)&outW[ob + 4] = make_float4(ww[4], ww[5], ww[6], ww[7]);

    cnt = __reduce_add_sync(0xffffffffu, cnt);
    if (lane == 0) s_cnt[wid] = cnt;
    __syncthreads();
    if (tid == 0) {
        int tot = 0;
#pragma unroll
        for (int w = 0; w < 8; w++) tot += s_cnt[w];
        outDv[row] = __fdiv_rn(1.0f, __fadd_rn((float)tot, 1e-10f));
    }
}

// ========== 4a) column-sum partials (1024 CTAs, streaming) ==================
__global__ void __launch_bounds__(256)
colsumA_kernel(const float* __restrict__ outH, const float* __restrict__ outW) {
    __shared__ float sH[2][128], sW[2][128];
    const int b = blockIdx.z;
    const int c = threadIdx.x & 127;
    const int col = blockIdx.x * 128 + c;
    const int half = threadIdx.x >> 7;
    const int r0 = blockIdx.y * 64 + half * 32;
    const float* Hb = outH + (size_t)b * NUMV * NUMV;
    const float* Wb = outW + (size_t)b * NUMV * NUMV;
    float sh = 0.0f, sw = 0.0f;
#pragma unroll 8
    for (int r = r0; r < r0 + 32; r++) {
        size_t idx = (size_t)r * NUMV + col;
        sh += Hb[idx];
        sw += Wb[idx];
    }
    sH[half][c] = sh; sW[half][c] = sw;
    __syncthreads();
    if (half == 0) {
        g_partH[b][blockIdx.y][col] = sH[0][c] + sH[1][c];
        g_partW[b][blockIdx.y][col] = sW[0][c] + sW[1][c];
    }
}

// ========== 4b) reduce partials -> De, colW; norm -> W_edge =================
__global__ void __launch_bounds__(512)
finalize_kernel(float* __restrict__ outDe, float* __restrict__ outWe) {
    __shared__ float red[16];
    __shared__ float s_den;
    const int b = blockIdx.x;
    const int tid = threadIdx.x;

    float cw[4];
    float ss = 0.0f;
#pragma unroll
    for (int j = 0; j < 4; j++) {
        int col = tid + j * 512;
        float th = 0.0f, tw = 0.0f;
#pragma unroll
        for (int ch = 0; ch < 32; ch++) {
            th += g_partH[b][ch][col];   // exact integers: order-free
            tw += g_partW[b][ch][col];
        }
        outDe[b * NUMV + col] = __fdiv_rn(1.0f, __fadd_rn(th, 1e-10f));
        cw[j] = tw;
        ss += tw * tw;
    }
#pragma unroll
    for (int off = 16; off >= 1; off >>= 1)
        ss += __shfl_xor_sync(0xffffffffu, ss, off);
    if ((tid & 31) == 0) red[tid >> 5] = ss;
    __syncthreads();
    if (tid == 0) {
        float t = 0.0f;
#pragma unroll
        for (int w = 0; w < 16; w++) t += red[w];
        s_den = fmaxf(__fsqrt_rn(t), 1e-12f);
    }
    __syncthreads();
    float d = s_den;
#pragma unroll
    for (int j = 0; j < 4; j++)
        outWe[b * NUMV + tid + j * 512] = __fdiv_rn(cw[j], d);
}

// ============================================================================
extern "C" void kernel_launch(void* const* d_in, const int* in_sizes, int n_in,
                              void* d_out, int out_size) {
    const float* H0 = (const float*)d_in[0];
    const float* vf = (const float*)d_in[1];
    const float* ef = (const float*)d_in[2];
    const float* Wq = (const float*)d_in[3];
    const float* bq = (const float*)d_in[4];
    const float* Wk = (const float*)d_in[5];
    const float* bk = (const float*)d_in[6];
    const void* iterp = (n_in >= 8) ? d_in[7] : (const void*)0;

    float* out = (float*)d_out;
    const size_t HW = (size_t)BSZ * NUMV * NUMV;   // 8388608
    float* outH  = out;
    float* outW  = out + HW;
    float* outDe = out + 2 * HW;
    float* outDv = outDe + BSZ * NUMV;
    float* outWe = outDv + BSZ * NUMV;
    (void)in_sizes; (void)out_size;

    proj_kernel<<<dim3(16, 2, 4), 256>>>(vf, ef, Wq, bq, Wk, bk);
    attn_kernel<<<dim3(32, 16, 2), 256>>>(H0);
    select_kernel<<<BSZ * NUMV, 256>>>(iterp, outH, outW, outDv);
    colsumA_kernel<<<dim3(16, 32, 2), 256>>>(outH, outW);
    finalize_kernel<<<BSZ, 512>>>(outDe, outWe);
}